// round 1
// baseline (speedup 1.0000x reference)
#include <cuda_runtime.h>
#include <cuda_bf16.h>

// LinearCRF: out = mean_b( logZ_b - gold_b )
// Strategy: linear-domain forward algorithm with exact power-of-2 renormalization.
// Row split into NCHUNK chunks; each chunk thread accumulates the 3x3 linear
// transfer matrix (mask==0 -> identity). Combiner chains alpha0 * M_c per row.

#define B_DIM   8192
#define L_DIM   1024
#define NCHUNK  8
#define CLEN    128          // L_DIM / NCHUNK
#define NGROUP  32           // CLEN / 4
#define COMB_BLOCKS  32
#define COMB_THREADS 256
#define LN2F 0.69314718055994530942f

__device__ float g_scratch[NCHUNK * 12 * B_DIM];   // [(c*12+k)*B + b]
__device__ float g_partials[COMB_BLOCKS];

// One forward step in linear domain (matrix form):
//   Mnew[i][j] = (sum_k M[i][k] * E[k][j]) * w_j,   w_j = exp(em_t[j])
// mask <= 0  => keep M (identity step). gold uses raw adjacent tags * mask.
#define STEP(e0v, e1v, e2v, tgv, mv) do {                                   \
    float w0 = __expf(e0v), w1 = __expf(e1v), w2 = __expf(e2v);             \
    float F00 = E00 * w0, F01 = E01 * w1, F02 = E02 * w2;                   \
    float F10 = E10 * w0, F11 = E11 * w1, F12 = E12 * w2;                   \
    float F20 = E20 * w0, F21 = E21 * w1, F22 = E22 * w2;                   \
    float n00 = fmaf(M02, F20, fmaf(M01, F10, M00 * F00));                  \
    float n01 = fmaf(M02, F21, fmaf(M01, F11, M00 * F01));                  \
    float n02 = fmaf(M02, F22, fmaf(M01, F12, M00 * F02));                  \
    float n10 = fmaf(M12, F20, fmaf(M11, F10, M10 * F00));                  \
    float n11 = fmaf(M12, F21, fmaf(M11, F11, M10 * F01));                  \
    float n12 = fmaf(M12, F22, fmaf(M11, F12, M10 * F02));                  \
    float n20 = fmaf(M22, F20, fmaf(M21, F10, M20 * F00));                  \
    float n21 = fmaf(M22, F21, fmaf(M21, F11, M20 * F01));                  \
    float n22 = fmaf(M22, F22, fmaf(M21, F12, M20 * F02));                  \
    bool u = (mv) > 0.f;                                                    \
    M00 = u ? n00 : M00; M01 = u ? n01 : M01; M02 = u ? n02 : M02;          \
    M10 = u ? n10 : M10; M11 = u ? n11 : M11; M12 = u ? n12 : M12;          \
    M20 = u ? n20 : M20; M21 = u ? n21 : M21; M22 = u ? n22 : M22;          \
    int tgl = (tgv);                                                        \
    float etg = (tgl == 0) ? (e0v) : ((tgl == 1) ? (e1v) : (e2v));          \
    float tr  = sT[ptag * 3 + tgl];                                         \
    gold = fmaf((mv), tr + etg, gold);                                      \
    ptag = tgl;                                                             \
} while (0)

__global__ void __launch_bounds__(128)
crf_chunk_kernel(const float* __restrict__ emissions,
                 const float* __restrict__ mask,
                 const float* __restrict__ transitions,
                 const int*   __restrict__ tags)
{
    __shared__ float sT[9];
    if (threadIdx.x < 9) sT[threadIdx.x] = transitions[threadIdx.x];
    __syncthreads();

    unsigned gtid = blockIdx.x * blockDim.x + threadIdx.x;   // [0, 65536)
    unsigned b = gtid & (B_DIM - 1);
    unsigned c = gtid >> 13;                                  // chunk 0..7

    float E00 = __expf(sT[0]), E01 = __expf(sT[1]), E02 = __expf(sT[2]);
    float E10 = __expf(sT[3]), E11 = __expf(sT[4]), E12 = __expf(sT[5]);
    float E20 = __expf(sT[6]), E21 = __expf(sT[7]), E22 = __expf(sT[8]);

    // Row/chunk base pointers (all 16B aligned: row strides 12288/4096 bytes)
    const float4* em4 = (const float4*)emissions + (size_t)b * 768 + (size_t)c * 96;
    const int4*   tg4 = (const int4*)tags        + (size_t)b * 256 + (size_t)c * 32;
    const float4* mk4 = (const float4*)mask      + (size_t)b * 256 + (size_t)c * 32;

    int ptag = tags[(size_t)b * L_DIM + (c ? (int)(c * CLEN) - 1 : 0)];

    float M00 = 1.f, M01 = 0.f, M02 = 0.f;
    float M10 = 0.f, M11 = 1.f, M12 = 0.f;
    float M20 = 0.f, M21 = 0.f, M22 = 1.f;
    float gold = 0.f;
    int esum = 0;

    // prime double buffer (group 0: steps c*128 .. c*128+3)
    float4 eA0 = em4[0], eA1 = em4[1], eA2 = em4[2];
    int4   tA  = tg4[0];
    float4 mA  = mk4[0];
    if (c == 0) mA.x = 0.f;   // t==0 is the init step, not a transition

    #pragma unroll 1
    for (int g = 0; g < NGROUP; ++g) {
        float4 eB0 = eA0, eB1 = eA1, eB2 = eA2;
        int4   tB  = tA;
        float4 mB  = mA;
        if (g + 1 < NGROUP) {
            eB0 = em4[(g + 1) * 3 + 0];
            eB1 = em4[(g + 1) * 3 + 1];
            eB2 = em4[(g + 1) * 3 + 2];
            tB  = tg4[g + 1];
            mB  = mk4[g + 1];
        }

        STEP(eA0.x, eA0.y, eA0.z, tA.x, mA.x);
        STEP(eA0.w, eA1.x, eA1.y, tA.y, mA.y);
        STEP(eA1.z, eA1.w, eA2.x, tA.z, mA.z);
        STEP(eA2.y, eA2.z, eA2.w, tA.w, mA.w);

        // exact renormalization: scale by 2^-ex where ex = ilogb(max entry)
        float mxa = fmaxf(fmaxf(M00, M01), M02);
        float mxb = fmaxf(fmaxf(M10, M11), M12);
        float mxc = fmaxf(fmaxf(M20, M21), M22);
        float mx  = fmaxf(fmaxf(mxa, mxb), mxc);
        int ex = (__float_as_int(mx) >> 23) - 127;         // mx > 0 always
        float sc = __int_as_float((127 - ex) << 23);       // 2^-ex, exact
        M00 *= sc; M01 *= sc; M02 *= sc;
        M10 *= sc; M11 *= sc; M12 *= sc;
        M20 *= sc; M21 *= sc; M22 *= sc;
        esum += ex;

        eA0 = eB0; eA1 = eB1; eA2 = eB2; tA = tB; mA = mB;
    }

    // coalesced store: consecutive lanes -> consecutive b
    float* s = g_scratch + (size_t)c * 12 * B_DIM + b;
    s[0 * B_DIM] = M00; s[1 * B_DIM] = M01; s[2 * B_DIM] = M02;
    s[3 * B_DIM] = M10; s[4 * B_DIM] = M11; s[5 * B_DIM] = M12;
    s[6 * B_DIM] = M20; s[7 * B_DIM] = M21; s[8 * B_DIM] = M22;
    s[9 * B_DIM]  = (float)esum;
    s[10 * B_DIM] = gold;
}

__global__ void __launch_bounds__(COMB_THREADS)
crf_combine_kernel(const float* __restrict__ emissions,
                   const float* __restrict__ mask,
                   const int*   __restrict__ tags)
{
    int b = blockIdx.x * blockDim.x + threadIdx.x;   // [0, 8192)

    float4 e4 = ((const float4*)emissions)[(size_t)b * 768];   // em[b,0,0..2] (+1 extra)
    float v0 = __expf(e4.x), v1 = __expf(e4.y), v2 = __expf(e4.z);

    int   tg0 = tags[(size_t)b * L_DIM];
    float m0  = mask[(size_t)b * L_DIM];
    float etg = (tg0 == 0) ? e4.x : ((tg0 == 1) ? e4.y : e4.z);
    float gold = etg * m0;
    float esum = 0.f;

    #pragma unroll
    for (int c = 0; c < NCHUNK; ++c) {
        const float* s = g_scratch + (size_t)c * 12 * B_DIM + b;
        float M00 = s[0 * B_DIM], M01 = s[1 * B_DIM], M02 = s[2 * B_DIM];
        float M10 = s[3 * B_DIM], M11 = s[4 * B_DIM], M12 = s[5 * B_DIM];
        float M20 = s[6 * B_DIM], M21 = s[7 * B_DIM], M22 = s[8 * B_DIM];
        esum += s[9 * B_DIM];
        gold += s[10 * B_DIM];

        float n0 = fmaf(v2, M20, fmaf(v1, M10, v0 * M00));
        float n1 = fmaf(v2, M21, fmaf(v1, M11, v0 * M01));
        float n2 = fmaf(v2, M22, fmaf(v1, M12, v0 * M02));

        float mx = fmaxf(fmaxf(n0, n1), n2);
        int ex = (__float_as_int(mx) >> 23) - 127;
        float sc = __int_as_float((127 - ex) << 23);
        v0 = n0 * sc; v1 = n1 * sc; v2 = n2 * sc;
        esum += (float)ex;
    }

    float logZ = __logf(v0 + v1 + v2) + esum * LN2F;
    float val  = logZ - gold;

    __shared__ float red[COMB_THREADS];
    red[threadIdx.x] = val;
    __syncthreads();
    #pragma unroll
    for (int s = COMB_THREADS / 2; s > 0; s >>= 1) {
        if (threadIdx.x < s) red[threadIdx.x] += red[threadIdx.x + s];
        __syncthreads();
    }
    if (threadIdx.x == 0) g_partials[blockIdx.x] = red[0];
}

__global__ void crf_final_kernel(float* __restrict__ out)
{
    float v = g_partials[threadIdx.x];   // 32 threads, 32 partials
    #pragma unroll
    for (int o = 16; o > 0; o >>= 1) v += __shfl_down_sync(0xffffffffu, v, o);
    if (threadIdx.x == 0) out[0] = v * (1.0f / (float)B_DIM);
}

extern "C" void kernel_launch(void* const* d_in, const int* in_sizes, int n_in,
                              void* d_out, int out_size)
{
    const float* emissions   = (const float*)d_in[0];
    const float* mask        = (const float*)d_in[1];
    const float* transitions = (const float*)d_in[2];
    const int*   tags        = (const int*)d_in[3];
    float* out = (float*)d_out;

    crf_chunk_kernel<<<(B_DIM * NCHUNK) / 128, 128>>>(emissions, mask, transitions, tags);
    crf_combine_kernel<<<COMB_BLOCKS, COMB_THREADS>>>(emissions, mask, tags);
    crf_final_kernel<<<1, 32>>>(out);
}